// round 5
// baseline (speedup 1.0000x reference)
#include <cuda_runtime.h>
#include <cuda_bf16.h>
#include <math.h>
#include <stdint.h>

#define TOK   2048
#define HD    512
#define FD    2048
#define NE    8
#define NSLOTS (TOK*2)

// ================= device scratch =================
__device__ int   g_count[NE];
__device__ int   g_base[NE];
__device__ int   g_cursor[NE];
__device__ int   g_topi[TOK*2];
__device__ float g_topw[TOK*2];
__device__ int   g_perm[NSLOTS];
__device__ float g_wt[NSLOTS];
__device__ int   g_slot_of[TOK*2];
__device__ __align__(16) uint32_t g_act[(size_t)NSLOTS*FD];   // packed (hi | lo<<16) bf16
__device__ __align__(16) float    g_y[(size_t)NSLOTS*HD];

// ================= PTX helpers (sm_80-portable only) =================
__device__ __forceinline__ uint32_t smem_u32(const void* p) {
    uint32_t a;
    asm("{ .reg .u64 t; cvta.to.shared.u64 t, %1; cvt.u32.u64 %0, t; }" : "=r"(a) : "l"(p));
    return a;
}
__device__ __forceinline__ void ldm4(uint32_t* r, uint32_t addr) {
    asm volatile("ldmatrix.sync.aligned.m8n8.x4.shared.b16 {%0,%1,%2,%3}, [%4];"
        : "=r"(r[0]), "=r"(r[1]), "=r"(r[2]), "=r"(r[3]) : "r"(addr));
}
__device__ __forceinline__ void ldm4t(uint32_t* r, uint32_t addr) {
    asm volatile("ldmatrix.sync.aligned.m8n8.x4.trans.shared.b16 {%0,%1,%2,%3}, [%4];"
        : "=r"(r[0]), "=r"(r[1]), "=r"(r[2]), "=r"(r[3]) : "r"(addr));
}
__device__ __forceinline__ void mma_bf16(float* c, const uint32_t* a, const uint32_t* b) {
    asm volatile("mma.sync.aligned.m16n8k16.row.col.f32.bf16.bf16.f32 "
        "{%0,%1,%2,%3}, {%4,%5,%6,%7}, {%8,%9}, {%0,%1,%2,%3};"
        : "+f"(c[0]), "+f"(c[1]), "+f"(c[2]), "+f"(c[3])
        : "r"(a[0]), "r"(a[1]), "r"(a[2]), "r"(a[3]), "r"(b[0]), "r"(b[1]));
}

// split 8 fp32 -> bf16 hi (uint4) + bf16 lo (uint4)
__device__ __forceinline__ void split8(const float* f, uint4& hi, uint4& lo) {
    uint32_t h[8], l[8];
#pragma unroll
    for (int i = 0; i < 8; i++) {
        __nv_bfloat16 hb = __float2bfloat16(f[i]);
        float r = f[i] - __bfloat162float(hb);
        h[i] = (uint32_t)__bfloat16_as_ushort(hb);
        l[i] = (uint32_t)__bfloat16_as_ushort(__float2bfloat16(r));
    }
    hi.x = h[0] | (h[1] << 16); hi.y = h[2] | (h[3] << 16);
    hi.z = h[4] | (h[5] << 16); hi.w = h[6] | (h[7] << 16);
    lo.x = l[0] | (l[1] << 16); lo.y = l[2] | (l[3] << 16);
    lo.z = l[4] | (l[5] << 16); lo.w = l[6] | (l[7] << 16);
}

// ================= routing =================
__global__ void zero_kernel() {
    int i = threadIdx.x;
    if (i < NE) { g_count[i] = 0; g_cursor[i] = 0; }
}

__global__ void router_kernel(const float* __restrict__ x,
                              const float* __restrict__ Wg) {
    int warp = threadIdx.x >> 5, lane = threadIdx.x & 31;
    int t = blockIdx.x * 8 + warp;
    if (t >= TOK) return;
    float acc[NE];
#pragma unroll
    for (int e = 0; e < NE; e++) acc[e] = 0.f;
    const float4* xr = (const float4*)(x + (size_t)t * HD);
#pragma unroll
    for (int it = 0; it < HD/128; it++) {
        int i = it * 32 + lane;
        float4 xv = xr[i];
#pragma unroll
        for (int e = 0; e < NE; e++) {
            float4 w = ((const float4*)(Wg + e*HD))[i];
            acc[e] += xv.x*w.x + xv.y*w.y + xv.z*w.z + xv.w*w.w;
        }
    }
#pragma unroll
    for (int off = 16; off > 0; off >>= 1)
#pragma unroll
        for (int e = 0; e < NE; e++)
            acc[e] += __shfl_xor_sync(0xffffffffu, acc[e], off);
    if (lane == 0) {
        int i0 = 0;
#pragma unroll
        for (int e = 1; e < NE; e++) if (acc[e] > acc[i0]) i0 = e;
        int i1 = (i0 == 0) ? 1 : 0;
#pragma unroll
        for (int e = 0; e < NE; e++)
            if (e != i0 && acc[e] > acc[i1]) i1 = e;
        float e1 = expf(acc[i1] - acc[i0]);
        float inv = 1.f / (1.f + e1);
        g_topi[t*2+0] = i0; g_topw[t*2+0] = inv;
        g_topi[t*2+1] = i1; g_topw[t*2+1] = e1 * inv;
        atomicAdd(&g_count[i0], 1);
        atomicAdd(&g_count[i1], 1);
    }
}

__global__ void scan_kernel() {
    int s = 0;
#pragma unroll
    for (int e = 0; e < NE; e++) { g_base[e] = s; s += g_count[e]; }
}

__global__ void scatter_kernel() {
    int t = blockIdx.x * 256 + threadIdx.x;
    if (t >= TOK) return;
#pragma unroll
    for (int k = 0; k < 2; k++) {
        int e = g_topi[t*2+k];
        int pos = atomicAdd(&g_cursor[e], 1);
        int slot = g_base[e] + pos;
        g_perm[slot] = t;
        g_wt[slot]   = g_topw[t*2+k];
        g_slot_of[t*2+k] = slot;
    }
}

// ================= grouped GEMM on mma.sync =================
// CTA tile 128x128, K-chunk 32, software-pipelined (reg prefetch).
// A smem [m][k] stride 40 (regular ldmatrix); B smem [k][n] stride 136 (trans ldmatrix).
// bf16x3: hi*hi + hi*lo + lo*hi. Weights read fp32 in ORIGINAL [k][n] layout.
// PASS1: C = silu(gather(x) @ W1 + b1) -> g_act packed bf16 pairs
// PASS2: C = (act @ W2 + b2) * wt     -> g_y fp32
#define APAD 40
#define BPAD 136

template<int KDIM, int NDIM, bool PASS1>
__global__ __launch_bounds__(256, 2)
void moe_gemm(const float* __restrict__ xsrc,     // x (PASS1) / unused (PASS2)
              const float* __restrict__ Wsrc,     // fp32 [E][KDIM][NDIM]
              const float* __restrict__ bias) {
    __shared__ __align__(16) __nv_bfloat16 sAhi[128*APAD];
    __shared__ __align__(16) __nv_bfloat16 sAlo[128*APAD];
    __shared__ __align__(16) __nv_bfloat16 sBhi[32*BPAD];
    __shared__ __align__(16) __nv_bfloat16 sBlo[32*BPAD];

    int e   = blockIdx.z;
    int cnt = g_count[e];
    int m0  = blockIdx.y * 128;
    if (m0 >= cnt) return;
    int n0   = blockIdx.x * 128;
    int base = g_base[e];

    int tid = threadIdx.x, wid = tid >> 5, lane = tid & 31;
    int wm = wid & 3, wn = wid >> 2;

    uint32_t aAhi = smem_u32(sAhi), aAlo = smem_u32(sAlo);
    uint32_t aBhi = smem_u32(sBhi), aBlo = smem_u32(sBlo);

    // A loader: 2 threads/row, 16 k-elems each
    int lrow = tid >> 1, lks = (tid & 1) * 16;
    int mrow = m0 + lrow; if (mrow >= cnt) mrow = cnt - 1;
    int arow = PASS1 ? g_perm[base + mrow] : (base + mrow);
    uint32_t sA_off = (uint32_t)(lrow * APAD + lks) * 2;
    const char* aGm = PASS1 ? (const char*)(xsrc + (size_t)arow * KDIM + lks)
                            : (const char*)(g_act + (size_t)arow * KDIM + lks);

    // B loader: 8 threads/row, 16 n-elems each
    int brow = tid >> 3, bcol = (tid & 7) * 16;
    uint32_t sB_off = (uint32_t)(brow * BPAD + bcol) * 2;
    const float* bGm = Wsrc + (size_t)e * KDIM * NDIM + (size_t)brow * NDIM + n0 + bcol;

    float acc[2][8][4];
#pragma unroll
    for (int a = 0; a < 2; a++)
#pragma unroll
        for (int b = 0; b < 8; b++)
#pragma unroll
            for (int c = 0; c < 4; c++) acc[a][b][c] = 0.f;

    // ldmatrix lane addressing
    int a_r = lane & 15, a_k = (lane >> 4) * 8;
    int bk_lane = ((lane >> 3) & 1) * 8 + (lane & 7);   // k-row within 16
    int bn_lane = (lane >> 4) * 8;                       // n offset within 16-block

    const int NCH = KDIM / 32;
    uint4 pfA[4];   // A prefetch: fp32x16 (PASS1) or packed u32 x16 (PASS2)
    float4 pfB[4];  // B prefetch: fp32 x16

    // prologue: prefetch chunk 0
#pragma unroll
    for (int g = 0; g < 4; g++) pfA[g] = *(const uint4*)(aGm + g*16);
#pragma unroll
    for (int g = 0; g < 4; g++) pfB[g] = *(const float4*)(bGm + g*4);

    for (int ci = 0; ci < NCH; ci++) {
        // ---- store staged regs to smem ----
        {
            uint4 hi0, lo0, hi1, lo1;
            if (PASS1) {
                float f[8];
                const float* pf = (const float*)pfA;
#pragma unroll
                for (int j = 0; j < 8; j++) f[j] = pf[j];
                split8(f, hi0, lo0);
#pragma unroll
                for (int j = 0; j < 8; j++) f[j] = pf[8+j];
                split8(f, hi1, lo1);
            } else {
                const uint32_t* p = (const uint32_t*)pfA;
                hi0.x = (p[0] & 0xFFFFu) | (p[1] << 16);  hi0.y = (p[2] & 0xFFFFu) | (p[3] << 16);
                hi0.z = (p[4] & 0xFFFFu) | (p[5] << 16);  hi0.w = (p[6] & 0xFFFFu) | (p[7] << 16);
                lo0.x = (p[0] >> 16) | (p[1] & 0xFFFF0000u); lo0.y = (p[2] >> 16) | (p[3] & 0xFFFF0000u);
                lo0.z = (p[4] >> 16) | (p[5] & 0xFFFF0000u); lo0.w = (p[6] >> 16) | (p[7] & 0xFFFF0000u);
                hi1.x = (p[8] & 0xFFFFu) | (p[9] << 16);  hi1.y = (p[10] & 0xFFFFu) | (p[11] << 16);
                hi1.z = (p[12] & 0xFFFFu) | (p[13] << 16); hi1.w = (p[14] & 0xFFFFu) | (p[15] << 16);
                lo1.x = (p[8] >> 16) | (p[9] & 0xFFFF0000u);  lo1.y = (p[10] >> 16) | (p[11] & 0xFFFF0000u);
                lo1.z = (p[12] >> 16) | (p[13] & 0xFFFF0000u); lo1.w = (p[14] >> 16) | (p[15] & 0xFFFF0000u);
            }
            *(uint4*)((char*)sAhi + sA_off)      = hi0;
            *(uint4*)((char*)sAhi + sA_off + 16) = hi1;
            *(uint4*)((char*)sAlo + sA_off)      = lo0;
            *(uint4*)((char*)sAlo + sA_off + 16) = lo1;

            float f[8];
            f[0]=pfB[0].x; f[1]=pfB[0].y; f[2]=pfB[0].z; f[3]=pfB[0].w;
            f[4]=pfB[1].x; f[5]=pfB[1].y; f[6]=pfB[1].z; f[7]=pfB[1].w;
            split8(f, hi0, lo0);
            f[0]=pfB[2].x; f[1]=pfB[2].y; f[2]=pfB[2].z; f[3]=pfB[2].w;
            f[4]=pfB[3].x; f[5]=pfB[3].y; f[6]=pfB[3].z; f[7]=pfB[3].w;
            split8(f, hi1, lo1);
            *(uint4*)((char*)sBhi + sB_off)      = hi0;
            *(uint4*)((char*)sBhi + sB_off + 16) = hi1;
            *(uint4*)((char*)sBlo + sB_off)      = lo0;
            *(uint4*)((char*)sBlo + sB_off + 16) = lo1;
        }
        __syncthreads();

        // ---- prefetch next chunk (latency hidden behind MMAs below) ----
        if (ci + 1 < NCH) {
            const char*  ap = aGm + (size_t)(ci + 1) * 32 * (PASS1 ? 4 : 4); // 32 elems * 4B each (fp32 or u32)
            const float* bp = bGm + (size_t)(ci + 1) * 32 * NDIM;
#pragma unroll
            for (int g = 0; g < 4; g++) pfA[g] = *(const uint4*)(ap + g*16);
#pragma unroll
            for (int g = 0; g < 4; g++) pfB[g] = *(const float4*)(bp + g*4);
        }

        // ---- compute: 2 K16 steps ----
#pragma unroll
        for (int kk = 0; kk < 2; kk++) {
            uint32_t ah[2][4], al[2][4];
#pragma unroll
            for (int mt = 0; mt < 2; mt++) {
                uint32_t off = (uint32_t)((wm*32 + mt*16 + a_r) * APAD + kk*16 + a_k) * 2;
                ldm4(ah[mt], aAhi + off);
                ldm4(al[mt], aAlo + off);
            }
#pragma unroll
            for (int p = 0; p < 4; p++) {
                uint32_t off = (uint32_t)((kk*16 + bk_lane) * BPAD + wn*64 + p*16 + bn_lane) * 2;
                uint32_t bh[4], bl[4];
                ldm4t(bh, aBhi + off);
                ldm4t(bl, aBlo + off);
#pragma unroll
                for (int mt = 0; mt < 2; mt++) {
#pragma unroll
                    for (int q = 0; q < 2; q++) {
                        float* c = acc[mt][p*2 + q];
                        mma_bf16(c, ah[mt], &bh[q*2]);
                        mma_bf16(c, ah[mt], &bl[q*2]);
                        mma_bf16(c, al[mt], &bh[q*2]);
                    }
                }
            }
        }
        __syncthreads();
    }

    // ---- epilogue ----
    int rbase = wm*32 + (lane >> 2);
    int cbase = n0 + wn*64 + (lane & 3)*2;
#pragma unroll
    for (int mt = 0; mt < 2; mt++) {
#pragma unroll
        for (int sub = 0; sub < 2; sub++) {
            int m = m0 + rbase + mt*16 + sub*8;
            if (m >= cnt) continue;
            int slot = base + m;
            float wtv = PASS1 ? 1.f : g_wt[slot];
#pragma unroll
            for (int nt = 0; nt < 8; nt++) {
                int n = cbase + nt*8;
                float v0 = acc[mt][nt][sub*2+0] + __ldg(&bias[e*NDIM + n]);
                float v1 = acc[mt][nt][sub*2+1] + __ldg(&bias[e*NDIM + n + 1]);
                if (PASS1) {
                    v0 = v0 / (1.f + __expf(-v0));
                    v1 = v1 / (1.f + __expf(-v1));
                    __nv_bfloat16 h0 = __float2bfloat16(v0);
                    __nv_bfloat16 h1 = __float2bfloat16(v1);
                    uint32_t l0 = (uint32_t)__bfloat16_as_ushort(__float2bfloat16(v0 - __bfloat162float(h0)));
                    uint32_t l1 = (uint32_t)__bfloat16_as_ushort(__float2bfloat16(v1 - __bfloat162float(h1)));
                    uint2 pk;
                    pk.x = (uint32_t)__bfloat16_as_ushort(h0) | (l0 << 16);
                    pk.y = (uint32_t)__bfloat16_as_ushort(h1) | (l1 << 16);
                    *(uint2*)(g_act + (size_t)slot * NDIM + n) = pk;
                } else {
                    float2 o; o.x = v0 * wtv; o.y = v1 * wtv;
                    *(float2*)(g_y + (size_t)slot * NDIM + n) = o;
                }
            }
        }
    }
}

// ================= combine =================
__global__ void combine_kernel(float* __restrict__ out) {
    int idx = blockIdx.x * 256 + threadIdx.x;
    if (idx >= TOK * (HD/4)) return;
    int t  = idx / (HD/4);
    int h4 = idx % (HD/4);
    int s0 = g_slot_of[t*2+0];
    int s1 = g_slot_of[t*2+1];
    float4 a = *(const float4*)&g_y[(size_t)s0 * HD + h4*4];
    float4 b = *(const float4*)&g_y[(size_t)s1 * HD + h4*4];
    float4 o;
    o.x = a.x + b.x; o.y = a.y + b.y; o.z = a.z + b.z; o.w = a.w + b.w;
    *(float4*)&out[(size_t)t * HD + h4*4] = o;
}

// ================= launch =================
extern "C" void kernel_launch(void* const* d_in, const int* in_sizes, int n_in,
                              void* d_out, int out_size) {
    const float* x  = (const float*)d_in[0];
    const float* Wg = (const float*)d_in[1];
    const float* W1 = (const float*)d_in[2];  // [8][512][2048]
    const float* b1 = (const float*)d_in[3];
    const float* W2 = (const float*)d_in[4];  // [8][2048][512]
    const float* b2 = (const float*)d_in[5];
    float* out = (float*)d_out;

    zero_kernel<<<1, 32>>>();
    router_kernel<<<TOK/8, 256>>>(x, Wg);
    scan_kernel<<<1, 1>>>();
    scatter_kernel<<<TOK/256, 256>>>();

    // Pass A: gather(x) @ W1 -> silu -> g_act (packed bf16 hi/lo)
    moe_gemm<HD, FD, true><<<dim3(FD/128, 32, NE), 256>>>(x, W1, b1);
    // Pass B: g_act @ W2 -> *wt -> g_y
    moe_gemm<FD, HD, false><<<dim3(HD/128, 32, NE), 256>>>(nullptr, W2, b2);

    combine_kernel<<<(TOK*(HD/4) + 255)/256, 256>>>(out);
}